// round 6
// baseline (speedup 1.0000x reference)
#include <cuda_runtime.h>
#include <cuda_bf16.h>
#include <mma.h>
using namespace nvcuda;

#define NBATCH 2048
#define NN 1024
#define NP 16
#define SSTRIDE 18433        // 1024 ablate + 1 pc2 + 1024 neuron + 16384 peptide
#define PC2_OFF 1024
#define NEU_OFF 1025
#define PEP_OFF 2049
#define DT_F (1.0f/120.0f)

#define UPD_THREADS 512
#define UPD_SMEM (NN*NP*4)   // 64KB peptide stage

// Scratch (allocation-free rule: __device__ globals)
__device__ __nv_bfloat16 g_fir16[(size_t)NBATCH*NN];
__device__ __nv_bfloat16 g_syn16[(size_t)NN*NN];
__device__ float g_dsyn[(size_t)NBATCH*NN];

__device__ __forceinline__ void cpa16(void* dst, const void* src) {
    asm volatile("cp.async.cg.shared.global [%0], [%1], 16;" ::
        "r"((unsigned)__cvta_generic_to_shared(dst)), "l"(src));
}

// ---------------------------------------------------------------------------
// K0: one-time synapse fp32 -> bf16
// ---------------------------------------------------------------------------
__global__ __launch_bounds__(256) void k_cvt(const float* __restrict__ syn)
{
    int i = blockIdx.x * 256 + threadIdx.x;          // NN*NN/4 threads
    float4 v = ((const float4*)syn)[i];
    __nv_bfloat162 lo = __floats2bfloat162_rn(v.x, v.y);
    __nv_bfloat162 hi = __floats2bfloat162_rn(v.z, v.w);
    ((__nv_bfloat162*)g_syn16)[i*2]     = lo;
    ((__nv_bfloat162*)g_syn16)[i*2 + 1] = hi;
}

// ---------------------------------------------------------------------------
// K1: firing = clip(-(relu(neuron)*ablate + 0.01)*log1p(-noise), 0, 10)
// ---------------------------------------------------------------------------
__global__ __launch_bounds__(256) void k_firing(
    const float* __restrict__ state, const float* __restrict__ noise_u,
    float* __restrict__ out_firing, float* __restrict__ out_state)
{
    int idx = blockIdx.x * 256 + threadIdx.x;   // exactly NBATCH*NN threads
    int row = idx >> 10;
    int n   = idx & (NN - 1);
    size_t base = (size_t)row * SSTRIDE;
    float ab    = state[base + n];
    float ne    = state[base + NEU_OFF + n];
    float noise = noise_u[idx];
    float f0  = fmaxf(ne, 0.0f) * ab;
    float fir = -(f0 + 0.01f) * log1pf(-noise);
    fir = fminf(fmaxf(fir, 0.0f), 10.0f);
    out_firing[idx] = fir;
    g_fir16[idx] = __float2bfloat16(fir);
    out_state[base + n] = ab;                       // ablate passthrough
    if (n == 0) out_state[base + PC2_OFF] = state[base + PC2_OFF];
}

// ---------------------------------------------------------------------------
// K2 v2: 64x128x32 tiles, 256 CTAs (fills 148 SMs), 3-stage cp.async
// pipeline, one __syncthreads per K step. 8 warps, warp tile 16x64.
// ---------------------------------------------------------------------------
__global__ __launch_bounds__(256) void k_gemm()
{
    __shared__ __nv_bfloat16 As[3][64][48];    // 3 x 6KB
    __shared__ __nv_bfloat16 Bs[3][32][144];   // 3 x 9KB
    const int bm = blockIdx.y, bn = blockIdx.x;
    const int tid = threadIdx.x;
    const int wid = tid >> 5;
    const int wm = wid >> 1;    // 0..3 -> 16-row slab
    const int wn = wid & 1;     // 0..1 -> 64-col slab

    const int ar  = tid >> 2, ac  = tid & 3;          // A: 64 rows x 4 uint4
    const int br0 = tid >> 4, bc0 = tid & 15;         // B: rows 0..15
    const int br1 = 16 + (tid >> 4), bc1 = tid & 15;  // B: rows 16..31

    const __nv_bfloat16* Ag = g_fir16 + (size_t)bm*64*NN;
    const __nv_bfloat16* Bg = g_syn16 + bn*128;

    wmma::fragment<wmma::accumulator,16,16,16,float> acc[4];
    #pragma unroll
    for (int j = 0; j < 4; j++) wmma::fill_fragment(acc[j], 0.0f);

    #pragma unroll
    for (int s = 0; s < 2; s++) {   // prologue: stages 0,1
        const int k0 = s*32;
        cpa16(&As[s][ar][ac*8],   Ag + (size_t)ar*NN + k0 + ac*8);
        cpa16(&Bs[s][br0][bc0*8], Bg + (size_t)(k0+br0)*NN + bc0*8);
        cpa16(&Bs[s][br1][bc1*8], Bg + (size_t)(k0+br1)*NN + bc1*8);
        asm volatile("cp.async.commit_group;");
    }

    for (int i = 0; i < 32; i++) {
        if (i < 31) asm volatile("cp.async.wait_group 1;");
        else        asm volatile("cp.async.wait_group 0;");
        __syncthreads();
        if (i + 2 < 32) {           // issue stage i+2 (buffer safe: all warps
            const int s = (i+2)%3;  // passed sync_i after mma_{i-1})
            const int k0 = (i+2)*32;
            cpa16(&As[s][ar][ac*8],   Ag + (size_t)ar*NN + k0 + ac*8);
            cpa16(&Bs[s][br0][bc0*8], Bg + (size_t)(k0+br0)*NN + bc0*8);
            cpa16(&Bs[s][br1][bc1*8], Bg + (size_t)(k0+br1)*NN + bc1*8);
            asm volatile("cp.async.commit_group;");
        }
        const int s = i % 3;
        #pragma unroll
        for (int kk = 0; kk < 32; kk += 16) {
            wmma::fragment<wmma::matrix_a,16,16,16,__nv_bfloat16,wmma::row_major> af;
            wmma::fragment<wmma::matrix_b,16,16,16,__nv_bfloat16,wmma::row_major> bf[4];
            wmma::load_matrix_sync(af, &As[s][wm*16][kk], 48);
            #pragma unroll
            for (int j = 0; j < 4; j++)
                wmma::load_matrix_sync(bf[j], &Bs[s][kk][wn*64 + j*16], 144);
            #pragma unroll
            for (int j = 0; j < 4; j++)
                wmma::mma_sync(acc[j], af, bf[j], acc[j]);
        }
    }
    #pragma unroll
    for (int j = 0; j < 4; j++)
        wmma::store_matrix_sync(
            g_dsyn + (size_t)(bm*64 + wm*16)*NN + bn*128 + wn*64 + j*16,
            acc[j], NN, wmma::mem_row_major);
}

// ---------------------------------------------------------------------------
// K3 v5: rolling y-registers in the stencil: thread walks consecutive y at
// fixed (x, channel); center of iter j is the up-neighbor of j+1, so only
// 3 LDS per site (down, left, right) instead of 5. Wrap via (j+1)&31 —
// pep_s is never overwritten, so reading y=0 at j=31 is safe.
// Store/stage maps unchanged (already optimal wavefronts).
// ---------------------------------------------------------------------------
__global__ __launch_bounds__(UPD_THREADS) void k_update(
    const float* __restrict__ state, const float* __restrict__ firing,
    const float* __restrict__ u, const float* __restrict__ D,
    const float* __restrict__ prod, const float* __restrict__ decay,
    const float* __restrict__ act, const float* __restrict__ ndecay,
    const float* __restrict__ input_layer, float* __restrict__ out_state)
{
    extern __shared__ float pep_s[];   // NN*NP, stride NP per neuron

    const int row = blockIdx.x;
    const int t = threadIdx.x;
    const size_t base = (size_t)row * SSTRIDE;
    const float* pep_g = state + base + PEP_OFF;
    float* outp = out_state + base + PEP_OFF;

    // Stage full peptide row: identity map, coalesced, deep MLP
    #pragma unroll 8
    for (int i = t; i < NN*NP; i += UPD_THREADS)
        pep_s[i] = pep_g[i];
    __syncthreads();

    const int p  = t & 15;      // peptide channel
    const int x0 = t >> 4;      // x coordinate (0..31)
    const int xl = (x0 + 31) & 31, xr = (x0 + 1) & 31;
    const float dd = fabsf(D[p]);
    const float pr = fabsf(prod[p]);
    const float de = fabsf(decay[p]);

    float cU = pep_s[(31*32 + x0)*NP + p];   // y = 31 (up-neighbor of y=0)
    float cC = pep_s[(        x0)*NP + p];   // y = 0

    #pragma unroll 8
    for (int j = 0; j < 32; j++) {           // j == y coordinate
        const int yd = (j + 1) & 31;
        const float cD  = pep_s[(yd*32 + x0)*NP + p];
        const float xlv = pep_s[(j*32 + xl)*NP + p];
        const float xrv = pep_s[(j*32 + xr)*NP + p];
        const float lap = cU + cD + xlv + xrv - 4.0f*cC;
        const float fir = firing[row*NN + j*32 + x0];
        outp[(j*32 + x0)*NP + p] = cC + DT_F*(pr*fir - de*cC + dd*lap);
        cU = cC; cC = cD;
    }
    __syncthreads();

    // Neuron integration: pepsum recomputed from smem (old peptide values)
    const float ndec = fabsf(ndecay[0]);
    const float uval = u[row];
    const float pc2  = state[base + PC2_OFF];
    const float4 a0 = *(const float4*)(act);
    const float4 a1 = *(const float4*)(act + 4);
    const float4 a2 = *(const float4*)(act + 8);
    const float4 a3 = *(const float4*)(act + 12);
    #pragma unroll
    for (int k = 0; k < 2; k++) {
        const int n = t + k*UPD_THREADS;
        const float* P = pep_s + n*NP;
        const float4 c0 = *(const float4*)(P);
        const float4 c1 = *(const float4*)(P + 4);
        const float4 c2 = *(const float4*)(P + 8);
        const float4 c3 = *(const float4*)(P + 12);
        float pepsum = c0.x*a0.x + c0.y*a0.y + c0.z*a0.z + c0.w*a0.w
                     + c1.x*a1.x + c1.y*a1.y + c1.z*a1.z + c1.w*a1.w
                     + c2.x*a2.x + c2.y*a2.y + c2.z*a2.z + c2.w*a2.w
                     + c3.x*a3.x + c3.y*a3.y + c3.z*a3.z + c3.w*a3.w;
        const float ab = state[base + n];
        const float ne = state[base + NEU_OFF + n] * ab;
        const float dn = pepsum*pc2 + g_dsyn[row*NN + n]
                       - ne*ndec + input_layer[n]*uval;
        out_state[base + NEU_OFF + n] = (ne + dn*DT_F) * ab;
    }
}

// ---------------------------------------------------------------------------
// Inputs (metadata order): u, state, noise_u, D, pep_prod_rate, pep_decay_rate,
// pep_action, synapse_matrix, neuron_decay, input_layer.
// Output: [firing (2048*1024) | state_new (2048*18433)] fp32.
// ---------------------------------------------------------------------------
extern "C" void kernel_launch(void* const* d_in, const int* in_sizes, int n_in,
                              void* d_out, int out_size)
{
    const float* u       = (const float*)d_in[0];
    const float* state   = (const float*)d_in[1];
    const float* noise_u = (const float*)d_in[2];
    const float* D       = (const float*)d_in[3];
    const float* prod    = (const float*)d_in[4];
    const float* decay   = (const float*)d_in[5];
    const float* act     = (const float*)d_in[6];
    const float* syn     = (const float*)d_in[7];
    const float* ndec    = (const float*)d_in[8];
    const float* inl     = (const float*)d_in[9];

    float* out        = (float*)d_out;
    float* out_firing = out;
    float* out_state  = out + (size_t)NBATCH*NN;

    // >48KB dynamic smem opt-in (sticky; not an allocation; capture-safe)
    cudaFuncSetAttribute(k_update, cudaFuncAttributeMaxDynamicSharedMemorySize,
                         UPD_SMEM);

    k_cvt<<<(NN*NN/4)/256, 256>>>(syn);
    k_firing<<<(NBATCH*NN)/256, 256>>>(state, noise_u, out_firing, out_state);

    dim3 gg(NN/128, NBATCH/64);   // 8 x 32 = 256 CTAs
    k_gemm<<<gg, 256>>>();

    k_update<<<NBATCH, UPD_THREADS, UPD_SMEM>>>(
        state, out_firing, u, D, prod, decay, act, ndec, inl, out_state);
}

// round 7
// speedup vs baseline: 1.0850x; 1.0850x over previous
#include <cuda_runtime.h>
#include <cuda_bf16.h>
#include <mma.h>
using namespace nvcuda;

#define NBATCH 2048
#define NN 1024
#define NP 16
#define SSTRIDE 18433        // 1024 ablate + 1 pc2 + 1024 neuron + 16384 peptide
#define PC2_OFF 1024
#define NEU_OFF 1025
#define PEP_OFF 2049
#define DT_F (1.0f/120.0f)

#define UPD_THREADS 512
#define UPD_SMEM ((NN*NP + NN) * 4)   // 64KB peptide + 4KB sums

// GEMM tiling: 64(m) x 128(n), K-stage 64, 3 stages
#define GA_STRIDE 72    // 64 + 8 pad (144B, 16B multiple)
#define GB_STRIDE 136   // 128 + 8 pad (272B, 16B multiple)
#define GEMM_SMEM (3*(64*GA_STRIDE + 64*GB_STRIDE)*2)   // 79872 B

// Scratch (allocation-free rule: __device__ globals)
__device__ __nv_bfloat16 g_fir16[(size_t)NBATCH*NN];
__device__ __nv_bfloat16 g_syn16[(size_t)NN*NN];
__device__ float g_dsyn[(size_t)NBATCH*NN];

__device__ __forceinline__ void cpa16(void* dst, const void* src) {
    asm volatile("cp.async.cg.shared.global [%0], [%1], 16;" ::
        "r"((unsigned)__cvta_generic_to_shared(dst)), "l"(src));
}

// ---------------------------------------------------------------------------
// K0: one-time synapse fp32 -> bf16
// ---------------------------------------------------------------------------
__global__ __launch_bounds__(256) void k_cvt(const float* __restrict__ syn)
{
    int i = blockIdx.x * 256 + threadIdx.x;          // NN*NN/4 threads
    float4 v = ((const float4*)syn)[i];
    __nv_bfloat162 lo = __floats2bfloat162_rn(v.x, v.y);
    __nv_bfloat162 hi = __floats2bfloat162_rn(v.z, v.w);
    ((__nv_bfloat162*)g_syn16)[i*2]     = lo;
    ((__nv_bfloat162*)g_syn16)[i*2 + 1] = hi;
}

// ---------------------------------------------------------------------------
// K1: firing = clip(-(relu(neuron)*ablate + 0.01)*log1p(-noise), 0, 10)
// ---------------------------------------------------------------------------
__global__ __launch_bounds__(256) void k_firing(
    const float* __restrict__ state, const float* __restrict__ noise_u,
    float* __restrict__ out_firing, float* __restrict__ out_state)
{
    int idx = blockIdx.x * 256 + threadIdx.x;   // exactly NBATCH*NN threads
    int row = idx >> 10;
    int n   = idx & (NN - 1);
    size_t base = (size_t)row * SSTRIDE;
    float ab    = state[base + n];
    float ne    = state[base + NEU_OFF + n];
    float noise = noise_u[idx];
    float f0  = fmaxf(ne, 0.0f) * ab;
    float fir = -(f0 + 0.01f) * log1pf(-noise);
    fir = fminf(fmaxf(fir, 0.0f), 10.0f);
    out_firing[idx] = fir;
    g_fir16[idx] = __float2bfloat16(fir);
    out_state[base + n] = ab;                       // ablate passthrough
    if (n == 0) out_state[base + PC2_OFF] = state[base + PC2_OFF];
}

// ---------------------------------------------------------------------------
// K2 v3: 64x128 tile, K=64 per stage (16 barriers total), 3-stage cp.async
// pipeline, 256 CTAs, 2 CTAs/SM (78KB dynamic smem).
// ---------------------------------------------------------------------------
__global__ __launch_bounds__(256) void k_gemm()
{
    extern __shared__ __nv_bfloat16 gsm[];
    __nv_bfloat16* As = gsm;                       // [3][64][GA_STRIDE]
    __nv_bfloat16* Bs = gsm + 3*64*GA_STRIDE;      // [3][64][GB_STRIDE]

    const int bm = blockIdx.y, bn = blockIdx.x;
    const int tid = threadIdx.x;
    const int wid = tid >> 5;
    const int wm = wid >> 1;    // 0..3 -> 16-row slab
    const int wn = wid & 1;     // 0..1 -> 64-col slab

    const __nv_bfloat16* Ag = g_fir16 + (size_t)bm*64*NN;
    const __nv_bfloat16* Bg = g_syn16 + bn*128;

    wmma::fragment<wmma::accumulator,16,16,16,float> acc[4];
    #pragma unroll
    for (int j = 0; j < 4; j++) wmma::fill_fragment(acc[j], 0.0f);

    // per-stage loaders: A 64x64 = 512 uint4 (2/thread), B 64x128 = 1024 uint4 (4/thread)
    auto load_stage = [&](int s, int k0) {
        __nv_bfloat16* Ab = As + s*64*GA_STRIDE;
        __nv_bfloat16* Bb = Bs + s*64*GB_STRIDE;
        #pragma unroll
        for (int j = 0; j < 2; j++) {
            int idx = tid + j*256;
            int r = idx >> 3, c = idx & 7;
            cpa16(Ab + r*GA_STRIDE + c*8, Ag + (size_t)r*NN + k0 + c*8);
        }
        #pragma unroll
        for (int j = 0; j < 4; j++) {
            int idx = tid + j*256;
            int r = idx >> 4, c = idx & 15;
            cpa16(Bb + r*GB_STRIDE + c*8, Bg + (size_t)(k0 + r)*NN + c*8);
        }
        asm volatile("cp.async.commit_group;");
    };

    load_stage(0, 0);
    load_stage(1, 64);

    for (int i = 0; i < 16; i++) {       // 16 K-steps of 64
        if (i < 15) asm volatile("cp.async.wait_group 1;");
        else        asm volatile("cp.async.wait_group 0;");
        __syncthreads();
        if (i + 2 < 16) load_stage((i+2)%3, (i+2)*64);

        const int s = i % 3;
        const __nv_bfloat16* Ab = As + s*64*GA_STRIDE;
        const __nv_bfloat16* Bb = Bs + s*64*GB_STRIDE;
        #pragma unroll
        for (int kk = 0; kk < 64; kk += 16) {
            wmma::fragment<wmma::matrix_a,16,16,16,__nv_bfloat16,wmma::row_major> af;
            wmma::fragment<wmma::matrix_b,16,16,16,__nv_bfloat16,wmma::row_major> bf[4];
            wmma::load_matrix_sync(af, Ab + (wm*16)*GA_STRIDE + kk, GA_STRIDE);
            #pragma unroll
            for (int j = 0; j < 4; j++)
                wmma::load_matrix_sync(bf[j], Bb + kk*GB_STRIDE + wn*64 + j*16, GB_STRIDE);
            #pragma unroll
            for (int j = 0; j < 4; j++)
                wmma::mma_sync(acc[j], af, bf[j], acc[j]);
        }
        __syncthreads();
    }
    #pragma unroll
    for (int j = 0; j < 4; j++)
        wmma::store_matrix_sync(
            g_dsyn + (size_t)(bm*64 + wm*16)*NN + bn*128 + wn*64 + j*16,
            acc[j], NN, wmma::mem_row_major);
}

// ---------------------------------------------------------------------------
// K3 v6: R5 stencil (5 independent LDS, unroll 8 — the fast form) +
// conflict-free pepsum reduction phase: lane l reads quad q=l&3 of neuron
// n_base+(l>>2) -> warp LDS.128 covers 512 contiguous bytes (4 wavefronts,
// no conflicts, vs 16 with the old n=t map); 2 shfl_xor fold the quad.
// ---------------------------------------------------------------------------
__global__ __launch_bounds__(UPD_THREADS) void k_update(
    const float* __restrict__ state, const float* __restrict__ firing,
    const float* __restrict__ u, const float* __restrict__ D,
    const float* __restrict__ prod, const float* __restrict__ decay,
    const float* __restrict__ act, const float* __restrict__ ndecay,
    const float* __restrict__ input_layer, float* __restrict__ out_state)
{
    extern __shared__ float sm_u[];
    float* pep_s = sm_u;            // NN*NP, stride NP per neuron
    float* sum_s = sm_u + NN*NP;    // NN

    const int row = blockIdx.x;
    const int t = threadIdx.x;
    const size_t base = (size_t)row * SSTRIDE;
    const float* pep_g = state + base + PEP_OFF;
    float* outp = out_state + base + PEP_OFF;

    // Stage full peptide row: identity map, coalesced, deep MLP
    #pragma unroll 8
    for (int i = t; i < NN*NP; i += UPD_THREADS)
        pep_s[i] = pep_g[i];
    __syncthreads();

    const int p  = t & 15;      // peptide channel
    const int x0 = t >> 4;      // x coordinate (0..31)
    const float dd = fabsf(D[p]);
    const float pr = fabsf(prod[p]);
    const float de = fabsf(decay[p]);

    #pragma unroll 8
    for (int j = 0; j < 32; j++) {          // j == y coordinate
        const int n  = j*32 + x0;
        const int yu = (j + 31) & 31, yd = (j + 1) & 31;
        const int xl = (x0 + 31) & 31, xr = (x0 + 1) & 31;
        const float c   = pep_s[n*NP + p];
        const float lap = pep_s[(yu*32 + x0)*NP + p]
                        + pep_s[(yd*32 + x0)*NP + p]
                        + pep_s[(j*32 + xl)*NP + p]
                        + pep_s[(j*32 + xr)*NP + p]
                        - 4.0f * c;
        const float fir = firing[row*NN + n];
        outp[n*NP + p] = c + DT_F*(pr*fir - de*c + dd*lap);
    }

    // pepsum reduction: 16 warps x 8 neurons/warp x 8 iters = 1024 neurons
    {
        const int lane = t & 31, w = t >> 5;
        const int q = lane & 3;               // quad within neuron
        const float4 aq = *(const float4*)(act + q*4);
        #pragma unroll
        for (int i = 0; i < 8; i++) {
            const int n = i*128 + w*8 + (lane >> 2);
            const float4 v = *(const float4*)(pep_s + n*NP + q*4);
            float part = v.x*aq.x + v.y*aq.y + v.z*aq.z + v.w*aq.w;
            part += __shfl_xor_sync(0xffffffffu, part, 1);
            part += __shfl_xor_sync(0xffffffffu, part, 2);
            if (q == 0) sum_s[n] = part;
        }
    }
    __syncthreads();

    // Neuron integration
    const float ndec = fabsf(ndecay[0]);
    const float uval = u[row];
    const float pc2  = state[base + PC2_OFF];
    #pragma unroll
    for (int k = 0; k < 2; k++) {
        const int n = t + k*UPD_THREADS;
        const float ab = state[base + n];
        const float ne = state[base + NEU_OFF + n] * ab;
        const float dn = sum_s[n]*pc2 + g_dsyn[row*NN + n]
                       - ne*ndec + input_layer[n]*uval;
        out_state[base + NEU_OFF + n] = (ne + dn*DT_F) * ab;
    }
}

// ---------------------------------------------------------------------------
// Inputs (metadata order): u, state, noise_u, D, pep_prod_rate, pep_decay_rate,
// pep_action, synapse_matrix, neuron_decay, input_layer.
// Output: [firing (2048*1024) | state_new (2048*18433)] fp32.
// ---------------------------------------------------------------------------
extern "C" void kernel_launch(void* const* d_in, const int* in_sizes, int n_in,
                              void* d_out, int out_size)
{
    const float* u       = (const float*)d_in[0];
    const float* state   = (const float*)d_in[1];
    const float* noise_u = (const float*)d_in[2];
    const float* D       = (const float*)d_in[3];
    const float* prod    = (const float*)d_in[4];
    const float* decay   = (const float*)d_in[5];
    const float* act     = (const float*)d_in[6];
    const float* syn     = (const float*)d_in[7];
    const float* ndec    = (const float*)d_in[8];
    const float* inl     = (const float*)d_in[9];

    float* out        = (float*)d_out;
    float* out_firing = out;
    float* out_state  = out + (size_t)NBATCH*NN;

    // >48KB dynamic smem opt-ins (sticky; not allocations; capture-safe)
    cudaFuncSetAttribute(k_update, cudaFuncAttributeMaxDynamicSharedMemorySize,
                         UPD_SMEM);
    cudaFuncSetAttribute(k_gemm, cudaFuncAttributeMaxDynamicSharedMemorySize,
                         GEMM_SMEM);

    k_cvt<<<(NN*NN/4)/256, 256>>>(syn);
    k_firing<<<(NBATCH*NN)/256, 256>>>(state, noise_u, out_firing, out_state);

    dim3 gg(NN/128, NBATCH/64);   // 8 x 32 = 256 CTAs
    k_gemm<<<gg, 256, GEMM_SMEM>>>();

    k_update<<<NBATCH, UPD_THREADS, UPD_SMEM>>>(
        state, out_firing, u, D, prod, decay, act, ndec, inl, out_state);
}

// round 8
// speedup vs baseline: 1.1837x; 1.0909x over previous
#include <cuda_runtime.h>
#include <cuda_bf16.h>
#include <mma.h>
using namespace nvcuda;

#define NBATCH 2048
#define NN 1024
#define NP 16
#define SSTRIDE 18433        // 1024 ablate + 1 pc2 + 1024 neuron + 16384 peptide
#define PC2_OFF 1024
#define NEU_OFF 1025
#define PEP_OFF 2049
#define DT_F (1.0f/120.0f)

// GEMM: 128(m) x 128(n) tile, K-stage 64, 3 stages, warp tile 16x128
#define GA_STRIDE 72    // 64 + 8 pad
#define GB_STRIDE 136   // 128 + 8 pad
#define GEMM_SMEM ((3*128*GA_STRIDE + 3*64*GB_STRIDE)*2)   // 107520 B

// Scratch (allocation-free rule: __device__ globals)
__device__ __nv_bfloat16 g_fir16[(size_t)NBATCH*NN];
__device__ __nv_bfloat16 g_syn16[(size_t)NN*NN];
__device__ float g_dsyn[(size_t)NBATCH*NN];

__device__ __forceinline__ void cpa16(void* dst, const void* src) {
    asm volatile("cp.async.cg.shared.global [%0], [%1], 16;" ::
        "r"((unsigned)__cvta_generic_to_shared(dst)), "l"(src));
}

// ---------------------------------------------------------------------------
// K0: one-time synapse fp32 -> bf16
// ---------------------------------------------------------------------------
__global__ __launch_bounds__(256) void k_cvt(const float* __restrict__ syn)
{
    int i = blockIdx.x * 256 + threadIdx.x;          // NN*NN/4 threads
    float4 v = ((const float4*)syn)[i];
    __nv_bfloat162 lo = __floats2bfloat162_rn(v.x, v.y);
    __nv_bfloat162 hi = __floats2bfloat162_rn(v.z, v.w);
    ((__nv_bfloat162*)g_syn16)[i*2]     = lo;
    ((__nv_bfloat162*)g_syn16)[i*2 + 1] = hi;
}

// ---------------------------------------------------------------------------
// K1: firing = clip(-(relu(neuron)*ablate + 0.01)*log1p(-noise), 0, 10)
// ---------------------------------------------------------------------------
__global__ __launch_bounds__(256) void k_firing(
    const float* __restrict__ state, const float* __restrict__ noise_u,
    float* __restrict__ out_firing, float* __restrict__ out_state)
{
    int idx = blockIdx.x * 256 + threadIdx.x;   // exactly NBATCH*NN threads
    int row = idx >> 10;
    int n   = idx & (NN - 1);
    size_t base = (size_t)row * SSTRIDE;
    float ab    = state[base + n];
    float ne    = state[base + NEU_OFF + n];
    float noise = noise_u[idx];
    float f0  = fmaxf(ne, 0.0f) * ab;
    float fir = -(f0 + 0.01f) * log1pf(-noise);
    fir = fminf(fmaxf(fir, 0.0f), 10.0f);
    out_firing[idx] = fir;
    g_fir16[idx] = __float2bfloat16(fir);
    out_state[base + n] = ab;                       // ablate passthrough
    if (n == 0) out_state[base + PC2_OFF] = state[base + PC2_OFF];
}

// ---------------------------------------------------------------------------
// K2 v4: 128x128 tile, warp tile 16x128 (8 independent accumulators/warp),
// K=64 per stage, 3-stage cp.async, 128 CTAs x 256 threads.
// ---------------------------------------------------------------------------
__global__ __launch_bounds__(256) void k_gemm()
{
    extern __shared__ __nv_bfloat16 gsm[];
    __nv_bfloat16* As = gsm;                        // [3][128][GA_STRIDE]
    __nv_bfloat16* Bs = gsm + 3*128*GA_STRIDE;      // [3][64][GB_STRIDE]

    const int bm = blockIdx.y, bn = blockIdx.x;
    const int tid = threadIdx.x;
    const int wid = tid >> 5;                       // warp m-slab (0..7)

    const __nv_bfloat16* Ag = g_fir16 + (size_t)bm*128*NN;
    const __nv_bfloat16* Bg = g_syn16 + bn*128;

    wmma::fragment<wmma::accumulator,16,16,16,float> acc[8];
    #pragma unroll
    for (int j = 0; j < 8; j++) wmma::fill_fragment(acc[j], 0.0f);

    // per-stage loaders: A 128x64 = 1024 uint4, B 64x128 = 1024 uint4 (4/thread each)
    auto load_stage = [&](int s, int k0) {
        __nv_bfloat16* Ab = As + s*128*GA_STRIDE;
        __nv_bfloat16* Bb = Bs + s*64*GB_STRIDE;
        #pragma unroll
        for (int j = 0; j < 4; j++) {
            int idx = tid + j*256;
            int r = idx >> 3, c = idx & 7;
            cpa16(Ab + r*GA_STRIDE + c*8, Ag + (size_t)r*NN + k0 + c*8);
        }
        #pragma unroll
        for (int j = 0; j < 4; j++) {
            int idx = tid + j*256;
            int r = idx >> 4, c = idx & 15;
            cpa16(Bb + r*GB_STRIDE + c*8, Bg + (size_t)(k0 + r)*NN + c*8);
        }
        asm volatile("cp.async.commit_group;");
    };

    load_stage(0, 0);
    load_stage(1, 64);

    for (int i = 0; i < 16; i++) {       // 16 K-steps of 64
        if (i < 15) asm volatile("cp.async.wait_group 1;");
        else        asm volatile("cp.async.wait_group 0;");
        __syncthreads();
        if (i + 2 < 16) load_stage((i+2)%3, (i+2)*64);

        const int s = i % 3;
        const __nv_bfloat16* Ab = As + s*128*GA_STRIDE;
        const __nv_bfloat16* Bb = Bs + s*64*GB_STRIDE;
        #pragma unroll
        for (int kk = 0; kk < 64; kk += 16) {
            wmma::fragment<wmma::matrix_a,16,16,16,__nv_bfloat16,wmma::row_major> af;
            wmma::load_matrix_sync(af, Ab + (wid*16)*GA_STRIDE + kk, GA_STRIDE);
            #pragma unroll
            for (int j = 0; j < 8; j++) {
                wmma::fragment<wmma::matrix_b,16,16,16,__nv_bfloat16,wmma::row_major> bf;
                wmma::load_matrix_sync(bf, Bb + kk*GB_STRIDE + j*16, GB_STRIDE);
                wmma::mma_sync(acc[j], af, bf, acc[j]);
            }
        }
        __syncthreads();
    }
    #pragma unroll
    for (int j = 0; j < 8; j++)
        wmma::store_matrix_sync(
            g_dsyn + (size_t)(bm*128 + wid*16)*NN + bn*128 + j*16,
            acc[j], NN, wmma::mem_row_major);
}

// ---------------------------------------------------------------------------
// K3 v7: TWO CTAs per batch row (y-halves, 16 rows each + 2 halo rows).
// 38KB static smem -> 4 CTAs/SM = 2048 threads = full occupancy.
// Access patterns identical to R7 (identity stage, p=t&15 stencil with
// 1-wavefront LDS/STG, quad-map pepsum) — only the y extent changed.
// ---------------------------------------------------------------------------
__global__ __launch_bounds__(512) void k_update(
    const float* __restrict__ state, const float* __restrict__ firing,
    const float* __restrict__ u, const float* __restrict__ D,
    const float* __restrict__ prod, const float* __restrict__ decay,
    const float* __restrict__ act, const float* __restrict__ ndecay,
    const float* __restrict__ input_layer, float* __restrict__ out_state)
{
    __shared__ float pep_s[18*512];   // 18 y-rows x 32 x x 16 p = 36KB
    __shared__ float sum_s[512];      // per-local-neuron pep*act sums

    const int row  = blockIdx.x >> 1;
    const int half = blockIdx.x & 1;
    const int y0   = half * 16;
    const int t = threadIdx.x;
    const size_t base = (size_t)row * SSTRIDE;
    const float* pep_g = state + base + PEP_OFF;
    float* outp = out_state + base + PEP_OFF;

    // Stage 18 y-rows (halo-inclusive): 18 per thread, coalesced
    #pragma unroll
    for (int i = t; i < 18*512; i += 512) {
        const int gy = (y0 + (i >> 9) + 31) & 31;    // y0 - 1 + ys, wrapped
        pep_s[i] = pep_g[gy*512 + (i & 511)];
    }
    __syncthreads();

    const int p  = t & 15;      // peptide channel
    const int xw = t >> 4;      // x coordinate (0..31)
    const int xl = (xw + 31) & 31, xr = (xw + 1) & 31;
    const float dd = fabsf(D[p]);
    const float pr = fabsf(prod[p]);
    const float de = fabsf(decay[p]);

    #pragma unroll 8
    for (int j = 0; j < 16; j++) {          // local y; smem ys = j+1
        const int ng = (y0 + j)*32 + xw;    // global neuron index
        const float c   = pep_s[(j+1)*512 + xw*16 + p];
        const float lap = pep_s[ j   *512 + xw*16 + p]
                        + pep_s[(j+2)*512 + xw*16 + p]
                        + pep_s[(j+1)*512 + xl*16 + p]
                        + pep_s[(j+1)*512 + xr*16 + p]
                        - 4.0f * c;
        const float fir = firing[row*NN + ng];
        outp[ng*NP + p] = c + DT_F*(pr*fir - de*c + dd*lap);
    }

    // pepsum over 512 local neurons: lane l -> quad q=l&3 of neuron w*8+(l>>2)
    // pep_s untouched since stage -> no barrier needed before this phase.
    {
        const int lane = t & 31, w = t >> 5;
        const int q = lane & 3;
        const float4 aq = *(const float4*)(act + q*4);
        #pragma unroll
        for (int i = 0; i < 4; i++) {
            const int nl = i*128 + w*8 + (lane >> 2);      // local neuron
            const float4 v = *(const float4*)(pep_s + 512 + nl*NP + q*4);
            float part = v.x*aq.x + v.y*aq.y + v.z*aq.z + v.w*aq.w;
            part += __shfl_xor_sync(0xffffffffu, part, 1);
            part += __shfl_xor_sync(0xffffffffu, part, 2);
            if (q == 0) sum_s[nl] = part;
        }
    }
    __syncthreads();

    // Neuron integration: 512 threads, one local neuron each
    const float ndec = fabsf(ndecay[0]);
    const float uval = u[row];
    const float pc2  = state[base + PC2_OFF];
    {
        const int ng = half*512 + t;
        const float ab = state[base + ng];
        const float ne = state[base + NEU_OFF + ng] * ab;
        const float dn = sum_s[t]*pc2 + g_dsyn[row*NN + ng]
                       - ne*ndec + input_layer[ng]*uval;
        out_state[base + NEU_OFF + ng] = (ne + dn*DT_F) * ab;
    }
}

// ---------------------------------------------------------------------------
// Inputs (metadata order): u, state, noise_u, D, pep_prod_rate, pep_decay_rate,
// pep_action, synapse_matrix, neuron_decay, input_layer.
// Output: [firing (2048*1024) | state_new (2048*18433)] fp32.
// ---------------------------------------------------------------------------
extern "C" void kernel_launch(void* const* d_in, const int* in_sizes, int n_in,
                              void* d_out, int out_size)
{
    const float* u       = (const float*)d_in[0];
    const float* state   = (const float*)d_in[1];
    const float* noise_u = (const float*)d_in[2];
    const float* D       = (const float*)d_in[3];
    const float* prod    = (const float*)d_in[4];
    const float* decay   = (const float*)d_in[5];
    const float* act     = (const float*)d_in[6];
    const float* syn     = (const float*)d_in[7];
    const float* ndec    = (const float*)d_in[8];
    const float* inl     = (const float*)d_in[9];

    float* out        = (float*)d_out;
    float* out_firing = out;
    float* out_state  = out + (size_t)NBATCH*NN;

    // >48KB dynamic smem opt-in for gemm (sticky; not an allocation)
    cudaFuncSetAttribute(k_gemm, cudaFuncAttributeMaxDynamicSharedMemorySize,
                         GEMM_SMEM);

    k_cvt<<<(NN*NN/4)/256, 256>>>(syn);
    k_firing<<<(NBATCH*NN)/256, 256>>>(state, noise_u, out_firing, out_state);

    dim3 gg(NN/128, NBATCH/128);   // 8 x 16 = 128 CTAs
    k_gemm<<<gg, 256, GEMM_SMEM>>>();

    k_update<<<NBATCH*2, 512>>>(
        state, out_firing, u, D, prod, decay, act, ndec, inl, out_state);
}

// round 9
// speedup vs baseline: 1.2863x; 1.0867x over previous
#include <cuda_runtime.h>
#include <cuda_bf16.h>
#include <mma.h>
using namespace nvcuda;

#define NBATCH 2048
#define NN 1024
#define NP 16
#define SSTRIDE 18433        // 1024 ablate + 1 pc2 + 1024 neuron + 16384 peptide
#define PC2_OFF 1024
#define NEU_OFF 1025
#define PEP_OFF 2049
#define DT_F (1.0f/120.0f)

// GEMM: 128(m) x 128(n) tile, split-K x2, K-stage 64, 3 stages
#define GA_STRIDE 72    // 64 + 8 pad
#define GB_STRIDE 136   // 128 + 8 pad
#define GEMM_SMEM ((3*128*GA_STRIDE + 3*64*GB_STRIDE)*2)   // 107520 B

// Scratch (allocation-free rule: __device__ globals)
__device__ __nv_bfloat16 g_fir16[(size_t)NBATCH*NN];
__device__ __nv_bfloat16 g_syn16[(size_t)NN*NN];
__device__ float g_dsyn [(size_t)NBATCH*NN];   // split-K partial 0
__device__ float g_dsyn2[(size_t)NBATCH*NN];   // split-K partial 1

__device__ __forceinline__ void cpa16(void* dst, const void* src) {
    asm volatile("cp.async.cg.shared.global [%0], [%1], 16;" ::
        "r"((unsigned)__cvta_generic_to_shared(dst)), "l"(src));
}

// ---------------------------------------------------------------------------
// K0: one-time synapse fp32 -> bf16
// ---------------------------------------------------------------------------
__global__ __launch_bounds__(256) void k_cvt(const float* __restrict__ syn)
{
    int i = blockIdx.x * 256 + threadIdx.x;          // NN*NN/4 threads
    float4 v = ((const float4*)syn)[i];
    __nv_bfloat162 lo = __floats2bfloat162_rn(v.x, v.y);
    __nv_bfloat162 hi = __floats2bfloat162_rn(v.z, v.w);
    ((__nv_bfloat162*)g_syn16)[i*2]     = lo;
    ((__nv_bfloat162*)g_syn16)[i*2 + 1] = hi;
}

// ---------------------------------------------------------------------------
// K1: firing = clip(-(relu(neuron)*ablate + 0.01)*log1p(-noise), 0, 10)
// ---------------------------------------------------------------------------
__global__ __launch_bounds__(256) void k_firing(
    const float* __restrict__ state, const float* __restrict__ noise_u,
    float* __restrict__ out_firing, float* __restrict__ out_state)
{
    int idx = blockIdx.x * 256 + threadIdx.x;   // exactly NBATCH*NN threads
    int row = idx >> 10;
    int n   = idx & (NN - 1);
    size_t base = (size_t)row * SSTRIDE;
    float ab    = state[base + n];
    float ne    = state[base + NEU_OFF + n];
    float noise = noise_u[idx];
    float f0  = fmaxf(ne, 0.0f) * ab;
    float fir = -(f0 + 0.01f) * log1pf(-noise);
    fir = fminf(fmaxf(fir, 0.0f), 10.0f);
    out_firing[idx] = fir;
    g_fir16[idx] = __float2bfloat16(fir);
    out_state[base + n] = ab;                       // ablate passthrough
    if (n == 0) out_state[base + PC2_OFF] = state[base + PC2_OFF];
}

// ---------------------------------------------------------------------------
// K2 v5: 128x128 tile, SPLIT-K x2 (gridDim.z): 256 CTAs fill 148 SMs at
// 2 CTAs/SM (107KB smem x2 = 214KB < 228KB carveout). Each CTA does K=512
// (8 steps of 64). Partials go to separate buffers (deterministic: the
// final 2-term add in k_update is order-independent).
// ---------------------------------------------------------------------------
__global__ __launch_bounds__(256) void k_gemm()
{
    extern __shared__ __nv_bfloat16 gsm[];
    __nv_bfloat16* As = gsm;                        // [3][128][GA_STRIDE]
    __nv_bfloat16* Bs = gsm + 3*128*GA_STRIDE;      // [3][64][GB_STRIDE]

    const int bm = blockIdx.y, bn = blockIdx.x, bk = blockIdx.z;
    const int tid = threadIdx.x;
    const int wid = tid >> 5;                       // warp m-slab (0..7)
    const int kbase = bk * 512;

    const __nv_bfloat16* Ag = g_fir16 + (size_t)bm*128*NN + kbase;
    const __nv_bfloat16* Bg = g_syn16 + (size_t)kbase*NN + bn*128;
    float* Cg = (bk == 0 ? g_dsyn : g_dsyn2);

    wmma::fragment<wmma::accumulator,16,16,16,float> acc[8];
    #pragma unroll
    for (int j = 0; j < 8; j++) wmma::fill_fragment(acc[j], 0.0f);

    auto load_stage = [&](int s, int k0) {
        __nv_bfloat16* Ab = As + s*128*GA_STRIDE;
        __nv_bfloat16* Bb = Bs + s*64*GB_STRIDE;
        #pragma unroll
        for (int j = 0; j < 4; j++) {
            int idx = tid + j*256;
            int r = idx >> 3, c = idx & 7;
            cpa16(Ab + r*GA_STRIDE + c*8, Ag + (size_t)r*NN + k0 + c*8);
        }
        #pragma unroll
        for (int j = 0; j < 4; j++) {
            int idx = tid + j*256;
            int r = idx >> 4, c = idx & 15;
            cpa16(Bb + r*GB_STRIDE + c*8, Bg + (size_t)(k0 + r)*NN + c*8);
        }
        asm volatile("cp.async.commit_group;");
    };

    load_stage(0, 0);
    load_stage(1, 64);

    for (int i = 0; i < 8; i++) {        // 8 K-steps of 64 (split-K half)
        if (i < 7) asm volatile("cp.async.wait_group 1;");
        else       asm volatile("cp.async.wait_group 0;");
        __syncthreads();
        if (i + 2 < 8) load_stage((i+2)%3, (i+2)*64);

        const int s = i % 3;
        const __nv_bfloat16* Ab = As + s*128*GA_STRIDE;
        const __nv_bfloat16* Bb = Bs + s*64*GB_STRIDE;
        #pragma unroll
        for (int kk = 0; kk < 64; kk += 16) {
            wmma::fragment<wmma::matrix_a,16,16,16,__nv_bfloat16,wmma::row_major> af;
            wmma::load_matrix_sync(af, Ab + (wid*16)*GA_STRIDE + kk, GA_STRIDE);
            #pragma unroll
            for (int j = 0; j < 8; j++) {
                wmma::fragment<wmma::matrix_b,16,16,16,__nv_bfloat16,wmma::row_major> bf;
                wmma::load_matrix_sync(bf, Bb + kk*GB_STRIDE + j*16, GB_STRIDE);
                wmma::mma_sync(acc[j], af, bf, acc[j]);
            }
        }
        __syncthreads();
    }
    #pragma unroll
    for (int j = 0; j < 8; j++)
        wmma::store_matrix_sync(
            Cg + (size_t)(bm*128 + wid*16)*NN + bn*128 + j*16,
            acc[j], NN, wmma::mem_row_major);
}

// ---------------------------------------------------------------------------
// K3 v8: 2 CTAs per batch row (y-halves + halo, 38KB static smem), stencil
// with preloaded CENTER REGISTER COLUMN c[18]: 18 independent LDS up front,
// then only 2 LDS (xl, xr) per site -> 50 LDS/thread vs 80 (no loop-carried
// chain, unlike R6's rolling version). Neuron phase sums both split-K
// partials.
// ---------------------------------------------------------------------------
__global__ __launch_bounds__(512) void k_update(
    const float* __restrict__ state, const float* __restrict__ firing,
    const float* __restrict__ u, const float* __restrict__ D,
    const float* __restrict__ prod, const float* __restrict__ decay,
    const float* __restrict__ act, const float* __restrict__ ndecay,
    const float* __restrict__ input_layer, float* __restrict__ out_state)
{
    __shared__ float pep_s[18*512];   // 18 y-rows x 32 x x 16 p = 36KB
    __shared__ float sum_s[512];

    const int row  = blockIdx.x >> 1;
    const int half = blockIdx.x & 1;
    const int y0   = half * 16;
    const int t = threadIdx.x;
    const size_t base = (size_t)row * SSTRIDE;
    const float* pep_g = state + base + PEP_OFF;
    float* outp = out_state + base + PEP_OFF;

    // Stage 18 y-rows (halo-inclusive): 18 per thread, coalesced
    #pragma unroll
    for (int i = t; i < 18*512; i += 512) {
        const int gy = (y0 + (i >> 9) + 31) & 31;    // y0 - 1 + ys, wrapped
        pep_s[i] = pep_g[gy*512 + (i & 511)];
    }
    __syncthreads();

    const int p  = t & 15;      // peptide channel
    const int xw = t >> 4;      // x coordinate (0..31)
    const int xl = (xw + 31) & 31, xr = (xw + 1) & 31;
    const float dd = fabsf(D[p]);
    const float pr = fabsf(prod[p]);
    const float de = fabsf(decay[p]);

    // Preload this thread's full y column (center + halos): independent LDS
    float c[18];
    #pragma unroll
    for (int ys = 0; ys < 18; ys++)
        c[ys] = pep_s[ys*512 + xw*16 + p];

    #pragma unroll
    for (int j = 0; j < 16; j++) {          // local y; smem ys = j+1
        const int ng = (y0 + j)*32 + xw;
        const float cc  = c[j+1];
        const float lap = c[j] + c[j+2]
                        + pep_s[(j+1)*512 + xl*16 + p]
                        + pep_s[(j+1)*512 + xr*16 + p]
                        - 4.0f * cc;
        const float fir = firing[row*NN + ng];
        outp[ng*NP + p] = cc + DT_F*(pr*fir - de*cc + dd*lap);
    }

    // pepsum: lane l -> quad q=l&3 of neuron w*8+(l>>2); pep_s untouched.
    {
        const int lane = t & 31, w = t >> 5;
        const int q = lane & 3;
        const float4 aq = *(const float4*)(act + q*4);
        #pragma unroll
        for (int i = 0; i < 4; i++) {
            const int nl = i*128 + w*8 + (lane >> 2);      // local neuron
            const float4 v = *(const float4*)(pep_s + 512 + nl*NP + q*4);
            float part = v.x*aq.x + v.y*aq.y + v.z*aq.z + v.w*aq.w;
            part += __shfl_xor_sync(0xffffffffu, part, 1);
            part += __shfl_xor_sync(0xffffffffu, part, 2);
            if (q == 0) sum_s[nl] = part;
        }
    }
    __syncthreads();

    // Neuron integration: 512 threads, one local neuron each
    const float ndec = fabsf(ndecay[0]);
    const float uval = u[row];
    const float pc2  = state[base + PC2_OFF];
    {
        const int ng = half*512 + t;
        const float ab = state[base + ng];
        const float ne = state[base + NEU_OFF + ng] * ab;
        const float syn = g_dsyn[row*NN + ng] + g_dsyn2[row*NN + ng];
        const float dn = sum_s[t]*pc2 + syn - ne*ndec + input_layer[ng]*uval;
        out_state[base + NEU_OFF + ng] = (ne + dn*DT_F) * ab;
    }
}

// ---------------------------------------------------------------------------
// Inputs (metadata order): u, state, noise_u, D, pep_prod_rate, pep_decay_rate,
// pep_action, synapse_matrix, neuron_decay, input_layer.
// Output: [firing (2048*1024) | state_new (2048*18433)] fp32.
// ---------------------------------------------------------------------------
extern "C" void kernel_launch(void* const* d_in, const int* in_sizes, int n_in,
                              void* d_out, int out_size)
{
    const float* u       = (const float*)d_in[0];
    const float* state   = (const float*)d_in[1];
    const float* noise_u = (const float*)d_in[2];
    const float* D       = (const float*)d_in[3];
    const float* prod    = (const float*)d_in[4];
    const float* decay   = (const float*)d_in[5];
    const float* act     = (const float*)d_in[6];
    const float* syn     = (const float*)d_in[7];
    const float* ndec    = (const float*)d_in[8];
    const float* inl     = (const float*)d_in[9];

    float* out        = (float*)d_out;
    float* out_firing = out;
    float* out_state  = out + (size_t)NBATCH*NN;

    // >48KB dynamic smem opt-in for gemm (sticky; not an allocation)
    cudaFuncSetAttribute(k_gemm, cudaFuncAttributeMaxDynamicSharedMemorySize,
                         GEMM_SMEM);

    k_cvt<<<(NN*NN/4)/256, 256>>>(syn);
    k_firing<<<(NBATCH*NN)/256, 256>>>(state, noise_u, out_firing, out_state);

    dim3 gg(NN/128, NBATCH/128, 2);   // 8 x 16 x 2 = 256 CTAs (split-K)
    k_gemm<<<gg, 256, GEMM_SMEM>>>();

    k_update<<<NBATCH*2, 512>>>(
        state, out_firing, u, D, prod, decay, act, ndec, inl, out_state);
}

// round 10
// speedup vs baseline: 1.3399x; 1.0416x over previous
#include <cuda_runtime.h>
#include <cuda_bf16.h>
#include <mma.h>
using namespace nvcuda;

#define NBATCH 2048
#define NN 1024
#define NP 16
#define SSTRIDE 18433        // 1024 ablate + 1 pc2 + 1024 neuron + 16384 peptide
#define PC2_OFF 1024
#define NEU_OFF 1025
#define PEP_OFF 2049
#define DT_F (1.0f/120.0f)

// GEMM: 128(m) x 128(n) tile, split-K x2, K-stage 64, 3 stages
#define GA_STRIDE 72    // 64 + 8 pad
#define GB_STRIDE 136   // 128 + 8 pad
#define GEMM_SMEM ((3*128*GA_STRIDE + 3*64*GB_STRIDE)*2)   // 107520 B

// Scratch (allocation-free rule: __device__ globals)
__device__ __nv_bfloat16 g_fir16[(size_t)NBATCH*NN];
__device__ __nv_bfloat16 g_syn16[(size_t)NN*NN];
__device__ float g_dsyn [(size_t)NBATCH*NN];   // split-K partial 0
__device__ float g_dsyn2[(size_t)NBATCH*NN];   // split-K partial 1

__device__ __forceinline__ void cpa16(void* dst, const void* src) {
    asm volatile("cp.async.cg.shared.global [%0], [%1], 16;" ::
        "r"((unsigned)__cvta_generic_to_shared(dst)), "l"(src));
}
__device__ __forceinline__ void cpa4(void* dst, const void* src) {
    asm volatile("cp.async.ca.shared.global [%0], [%1], 4;" ::
        "r"((unsigned)__cvta_generic_to_shared(dst)), "l"(src));
}

// ---------------------------------------------------------------------------
// K0: one-time synapse fp32 -> bf16
// ---------------------------------------------------------------------------
__global__ __launch_bounds__(256) void k_cvt(const float* __restrict__ syn)
{
    int i = blockIdx.x * 256 + threadIdx.x;          // NN*NN/4 threads
    float4 v = ((const float4*)syn)[i];
    __nv_bfloat162 lo = __floats2bfloat162_rn(v.x, v.y);
    __nv_bfloat162 hi = __floats2bfloat162_rn(v.z, v.w);
    ((__nv_bfloat162*)g_syn16)[i*2]     = lo;
    ((__nv_bfloat162*)g_syn16)[i*2 + 1] = hi;
}

// ---------------------------------------------------------------------------
// K1: firing = clip(-(relu(neuron)*ablate + 0.01)*log1p(-noise), 0, 10)
// ---------------------------------------------------------------------------
__global__ __launch_bounds__(256) void k_firing(
    const float* __restrict__ state, const float* __restrict__ noise_u,
    float* __restrict__ out_firing, float* __restrict__ out_state)
{
    int idx = blockIdx.x * 256 + threadIdx.x;   // exactly NBATCH*NN threads
    int row = idx >> 10;
    int n   = idx & (NN - 1);
    size_t base = (size_t)row * SSTRIDE;
    float ab    = state[base + n];
    float ne    = state[base + NEU_OFF + n];
    float noise = noise_u[idx];
    float f0  = fmaxf(ne, 0.0f) * ab;
    float fir = -(f0 + 0.01f) * log1pf(-noise);
    fir = fminf(fmaxf(fir, 0.0f), 10.0f);
    out_firing[idx] = fir;
    g_fir16[idx] = __float2bfloat16(fir);
    out_state[base + n] = ab;                       // ablate passthrough
    if (n == 0) out_state[base + PC2_OFF] = state[base + PC2_OFF];
}

// ---------------------------------------------------------------------------
// K2 v6: 128x128 tile, split-K x2 (256 CTAs, 2/SM). Warp grid 4(m) x 2(n),
// warp tile 32x64: per kk 2 af + 4 bf fragment loads for 8 mma (was 1+8 for
// 8) -> 33% fewer smem fragment loads, B redundancy 8x -> 4x.
// ---------------------------------------------------------------------------
__global__ __launch_bounds__(256) void k_gemm()
{
    extern __shared__ __nv_bfloat16 gsm[];
    __nv_bfloat16* As = gsm;                        // [3][128][GA_STRIDE]
    __nv_bfloat16* Bs = gsm + 3*128*GA_STRIDE;      // [3][64][GB_STRIDE]

    const int bm = blockIdx.y, bn = blockIdx.x, bk = blockIdx.z;
    const int tid = threadIdx.x;
    const int wid = tid >> 5;
    const int wm = wid >> 1;    // 0..3 -> 32-row slab
    const int wn = wid & 1;     // 0..1 -> 64-col slab
    const int kbase = bk * 512;

    const __nv_bfloat16* Ag = g_fir16 + (size_t)bm*128*NN + kbase;
    const __nv_bfloat16* Bg = g_syn16 + (size_t)kbase*NN + bn*128;
    float* Cg = (bk == 0 ? g_dsyn : g_dsyn2);

    wmma::fragment<wmma::accumulator,16,16,16,float> acc[2][4];
    #pragma unroll
    for (int i = 0; i < 2; i++)
        #pragma unroll
        for (int j = 0; j < 4; j++) wmma::fill_fragment(acc[i][j], 0.0f);

    auto load_stage = [&](int s, int k0) {
        __nv_bfloat16* Ab = As + s*128*GA_STRIDE;
        __nv_bfloat16* Bb = Bs + s*64*GB_STRIDE;
        #pragma unroll
        for (int j = 0; j < 4; j++) {
            int idx = tid + j*256;
            int r = idx >> 3, c = idx & 7;
            cpa16(Ab + r*GA_STRIDE + c*8, Ag + (size_t)r*NN + k0 + c*8);
        }
        #pragma unroll
        for (int j = 0; j < 4; j++) {
            int idx = tid + j*256;
            int r = idx >> 4, c = idx & 15;
            cpa16(Bb + r*GB_STRIDE + c*8, Bg + (size_t)(k0 + r)*NN + c*8);
        }
        asm volatile("cp.async.commit_group;");
    };

    load_stage(0, 0);
    load_stage(1, 64);

    for (int i = 0; i < 8; i++) {        // 8 K-steps of 64 (split-K half)
        if (i < 7) asm volatile("cp.async.wait_group 1;");
        else       asm volatile("cp.async.wait_group 0;");
        __syncthreads();
        if (i + 2 < 8) load_stage((i+2)%3, (i+2)*64);

        const int s = i % 3;
        const __nv_bfloat16* Ab = As + s*128*GA_STRIDE;
        const __nv_bfloat16* Bb = Bs + s*64*GB_STRIDE;
        #pragma unroll
        for (int kk = 0; kk < 64; kk += 16) {
            wmma::fragment<wmma::matrix_a,16,16,16,__nv_bfloat16,wmma::row_major> af[2];
            wmma::fragment<wmma::matrix_b,16,16,16,__nv_bfloat16,wmma::row_major> bf[4];
            #pragma unroll
            for (int ii = 0; ii < 2; ii++)
                wmma::load_matrix_sync(af[ii], Ab + (wm*32 + ii*16)*GA_STRIDE + kk, GA_STRIDE);
            #pragma unroll
            for (int j = 0; j < 4; j++)
                wmma::load_matrix_sync(bf[j], Bb + kk*GB_STRIDE + wn*64 + j*16, GB_STRIDE);
            #pragma unroll
            for (int ii = 0; ii < 2; ii++)
                #pragma unroll
                for (int j = 0; j < 4; j++)
                    wmma::mma_sync(acc[ii][j], af[ii], bf[j], acc[ii][j]);
        }
        __syncthreads();
    }
    #pragma unroll
    for (int ii = 0; ii < 2; ii++)
        #pragma unroll
        for (int j = 0; j < 4; j++)
            wmma::store_matrix_sync(
                Cg + (size_t)(bm*128 + wm*32 + ii*16)*NN + bn*128 + wn*64 + j*16,
                acc[ii][j], NN, wmma::mem_row_major);
}

// ---------------------------------------------------------------------------
// K3 v9: as R9 (2 CTAs/row, c[18] register column, quad pepsum) but the
// peptide staging uses 4-byte cp.async: 1 L1 op per element instead of
// LDG+STS (region is only 4B aligned -> cannot vectorize).
// ---------------------------------------------------------------------------
__global__ __launch_bounds__(512) void k_update(
    const float* __restrict__ state, const float* __restrict__ firing,
    const float* __restrict__ u, const float* __restrict__ D,
    const float* __restrict__ prod, const float* __restrict__ decay,
    const float* __restrict__ act, const float* __restrict__ ndecay,
    const float* __restrict__ input_layer, float* __restrict__ out_state)
{
    __shared__ float pep_s[18*512];   // 18 y-rows x 32 x x 16 p = 36KB
    __shared__ float sum_s[512];

    const int row  = blockIdx.x >> 1;
    const int half = blockIdx.x & 1;
    const int y0   = half * 16;
    const int t = threadIdx.x;
    const size_t base = (size_t)row * SSTRIDE;
    const float* pep_g = state + base + PEP_OFF;
    float* outp = out_state + base + PEP_OFF;

    // Stage 18 y-rows (halo-inclusive) via 4B cp.async, coalesced
    #pragma unroll
    for (int i = t; i < 18*512; i += 512) {
        const int gy = (y0 + (i >> 9) + 31) & 31;    // y0 - 1 + ys, wrapped
        cpa4(&pep_s[i], pep_g + gy*512 + (i & 511));
    }
    asm volatile("cp.async.commit_group;");
    asm volatile("cp.async.wait_group 0;");
    __syncthreads();

    const int p  = t & 15;      // peptide channel
    const int xw = t >> 4;      // x coordinate (0..31)
    const int xl = (xw + 31) & 31, xr = (xw + 1) & 31;
    const float dd = fabsf(D[p]);
    const float pr = fabsf(prod[p]);
    const float de = fabsf(decay[p]);

    // Preload this thread's full y column (center + halos): independent LDS
    float c[18];
    #pragma unroll
    for (int ys = 0; ys < 18; ys++)
        c[ys] = pep_s[ys*512 + xw*16 + p];

    #pragma unroll
    for (int j = 0; j < 16; j++) {          // local y; smem ys = j+1
        const int ng = (y0 + j)*32 + xw;
        const float cc  = c[j+1];
        const float lap = c[j] + c[j+2]
                        + pep_s[(j+1)*512 + xl*16 + p]
                        + pep_s[(j+1)*512 + xr*16 + p]
                        - 4.0f * cc;
        const float fir = firing[row*NN + ng];
        outp[ng*NP + p] = cc + DT_F*(pr*fir - de*cc + dd*lap);
    }

    // pepsum: lane l -> quad q=l&3 of neuron w*8+(l>>2); pep_s untouched.
    {
        const int lane = t & 31, w = t >> 5;
        const int q = lane & 3;
        const float4 aq = *(const float4*)(act + q*4);
        #pragma unroll
        for (int i = 0; i < 4; i++) {
            const int nl = i*128 + w*8 + (lane >> 2);      // local neuron
            const float4 v = *(const float4*)(pep_s + 512 + nl*NP + q*4);
            float part = v.x*aq.x + v.y*aq.y + v.z*aq.z + v.w*aq.w;
            part += __shfl_xor_sync(0xffffffffu, part, 1);
            part += __shfl_xor_sync(0xffffffffu, part, 2);
            if (q == 0) sum_s[nl] = part;
        }
    }
    __syncthreads();

    // Neuron integration: 512 threads, one local neuron each
    const float ndec = fabsf(ndecay[0]);
    const float uval = u[row];
    const float pc2  = state[base + PC2_OFF];
    {
        const int ng = half*512 + t;
        const float ab = state[base + ng];
        const float ne = state[base + NEU_OFF + ng] * ab;
        const float syn = g_dsyn[row*NN + ng] + g_dsyn2[row*NN + ng];
        const float dn = sum_s[t]*pc2 + syn - ne*ndec + input_layer[ng]*uval;
        out_state[base + NEU_OFF + ng] = (ne + dn*DT_F) * ab;
    }
}

// ---------------------------------------------------------------------------
// Inputs (metadata order): u, state, noise_u, D, pep_prod_rate, pep_decay_rate,
// pep_action, synapse_matrix, neuron_decay, input_layer.
// Output: [firing (2048*1024) | state_new (2048*18433)] fp32.
// ---------------------------------------------------------------------------
extern "C" void kernel_launch(void* const* d_in, const int* in_sizes, int n_in,
                              void* d_out, int out_size)
{
    const float* u       = (const float*)d_in[0];
    const float* state   = (const float*)d_in[1];
    const float* noise_u = (const float*)d_in[2];
    const float* D       = (const float*)d_in[3];
    const float* prod    = (const float*)d_in[4];
    const float* decay   = (const float*)d_in[5];
    const float* act     = (const float*)d_in[6];
    const float* syn     = (const float*)d_in[7];
    const float* ndec    = (const float*)d_in[8];
    const float* inl     = (const float*)d_in[9];

    float* out        = (float*)d_out;
    float* out_firing = out;
    float* out_state  = out + (size_t)NBATCH*NN;

    // >48KB dynamic smem opt-in for gemm (sticky; not an allocation)
    cudaFuncSetAttribute(k_gemm, cudaFuncAttributeMaxDynamicSharedMemorySize,
                         GEMM_SMEM);

    k_cvt<<<(NN*NN/4)/256, 256>>>(syn);
    k_firing<<<(NBATCH*NN)/256, 256>>>(state, noise_u, out_firing, out_state);

    dim3 gg(NN/128, NBATCH/128, 2);   // 8 x 16 x 2 = 256 CTAs (split-K)
    k_gemm<<<gg, 256, GEMM_SMEM>>>();

    k_update<<<NBATCH*2, 512>>>(
        state, out_firing, u, D, prod, decay, act, ndec, inl, out_state);
}

// round 11
// speedup vs baseline: 1.3666x; 1.0200x over previous
#include <cuda_runtime.h>
#include <cuda_bf16.h>
#include <mma.h>
using namespace nvcuda;

#define NBATCH 2048
#define NN 1024
#define NP 16
#define SSTRIDE 18433        // 1024 ablate + 1 pc2 + 1024 neuron + 16384 peptide
#define PC2_OFF 1024
#define NEU_OFF 1025
#define PEP_OFF 2049
#define DT_F (1.0f/120.0f)

// GEMM: 128(m) x 128(n) tile, split-K x2, K-stage 64, 3 stages
#define GA_STRIDE 72    // 64 + 8 pad
#define GB_STRIDE 136   // 128 + 8 pad
#define GEMM_SMEM ((3*128*GA_STRIDE + 3*64*GB_STRIDE)*2)   // 107520 B

// Scratch (allocation-free rule: __device__ globals)
__device__ __nv_bfloat16 g_fir16[(size_t)NBATCH*NN];
__device__ __nv_bfloat16 g_syn16[(size_t)NN*NN];
__device__ float g_dsyn [(size_t)NBATCH*NN];   // split-K partial 0
__device__ float g_dsyn2[(size_t)NBATCH*NN];   // split-K partial 1
__device__ float g_psum [(size_t)NBATCH*NN];   // per-neuron sum(pep*act)

__device__ __forceinline__ void cpa16(void* dst, const void* src) {
    asm volatile("cp.async.cg.shared.global [%0], [%1], 16;" ::
        "r"((unsigned)__cvta_generic_to_shared(dst)), "l"(src));
}

// ---------------------------------------------------------------------------
// K0: one-time synapse fp32 -> bf16 (side stream, hidden under k_firing)
// ---------------------------------------------------------------------------
__global__ __launch_bounds__(256) void k_cvt(const float* __restrict__ syn)
{
    int i = blockIdx.x * 256 + threadIdx.x;          // NN*NN/4 threads
    float4 v = ((const float4*)syn)[i];
    __nv_bfloat162 lo = __floats2bfloat162_rn(v.x, v.y);
    __nv_bfloat162 hi = __floats2bfloat162_rn(v.z, v.w);
    ((__nv_bfloat162*)g_syn16)[i*2]     = lo;
    ((__nv_bfloat162*)g_syn16)[i*2 + 1] = hi;
}

// ---------------------------------------------------------------------------
// K1: firing = clip(-(relu(neuron)*ablate + 0.01)*log1p(-noise), 0, 10)
// ---------------------------------------------------------------------------
__global__ __launch_bounds__(256) void k_firing(
    const float* __restrict__ state, const float* __restrict__ noise_u,
    float* __restrict__ out_firing, float* __restrict__ out_state)
{
    int idx = blockIdx.x * 256 + threadIdx.x;   // exactly NBATCH*NN threads
    int row = idx >> 10;
    int n   = idx & (NN - 1);
    size_t base = (size_t)row * SSTRIDE;
    float ab    = state[base + n];
    float ne    = state[base + NEU_OFF + n];
    float noise = noise_u[idx];
    float f0  = fmaxf(ne, 0.0f) * ab;
    float fir = -(f0 + 0.01f) * log1pf(-noise);
    fir = fminf(fmaxf(fir, 0.0f), 10.0f);
    out_firing[idx] = fir;
    g_fir16[idx] = __float2bfloat16(fir);
    out_state[base + n] = ab;                       // ablate passthrough
    if (n == 0) out_state[base + PC2_OFF] = state[base + PC2_OFF];
}

// ---------------------------------------------------------------------------
// K2: 128x128 tile, split-K x2, warp grid 4x2 (warp tile 32x64), K=64/stage,
// 3-stage cp.async. Runs on side stream CONCURRENT with k_pep.
// ---------------------------------------------------------------------------
__global__ __launch_bounds__(256) void k_gemm()
{
    extern __shared__ __nv_bfloat16 gsm[];
    __nv_bfloat16* As = gsm;                        // [3][128][GA_STRIDE]
    __nv_bfloat16* Bs = gsm + 3*128*GA_STRIDE;      // [3][64][GB_STRIDE]

    const int bm = blockIdx.y, bn = blockIdx.x, bk = blockIdx.z;
    const int tid = threadIdx.x;
    const int wid = tid >> 5;
    const int wm = wid >> 1;    // 0..3 -> 32-row slab
    const int wn = wid & 1;     // 0..1 -> 64-col slab
    const int kbase = bk * 512;

    const __nv_bfloat16* Ag = g_fir16 + (size_t)bm*128*NN + kbase;
    const __nv_bfloat16* Bg = g_syn16 + (size_t)kbase*NN + bn*128;
    float* Cg = (bk == 0 ? g_dsyn : g_dsyn2);

    wmma::fragment<wmma::accumulator,16,16,16,float> acc[2][4];
    #pragma unroll
    for (int i = 0; i < 2; i++)
        #pragma unroll
        for (int j = 0; j < 4; j++) wmma::fill_fragment(acc[i][j], 0.0f);

    auto load_stage = [&](int s, int k0) {
        __nv_bfloat16* Ab = As + s*128*GA_STRIDE;
        __nv_bfloat16* Bb = Bs + s*64*GB_STRIDE;
        #pragma unroll
        for (int j = 0; j < 4; j++) {
            int idx = tid + j*256;
            int r = idx >> 3, c = idx & 7;
            cpa16(Ab + r*GA_STRIDE + c*8, Ag + (size_t)r*NN + k0 + c*8);
        }
        #pragma unroll
        for (int j = 0; j < 4; j++) {
            int idx = tid + j*256;
            int r = idx >> 4, c = idx & 15;
            cpa16(Bb + r*GB_STRIDE + c*8, Bg + (size_t)(k0 + r)*NN + c*8);
        }
        asm volatile("cp.async.commit_group;");
    };

    load_stage(0, 0);
    load_stage(1, 64);

    for (int i = 0; i < 8; i++) {        // 8 K-steps of 64 (split-K half)
        if (i < 7) asm volatile("cp.async.wait_group 1;");
        else       asm volatile("cp.async.wait_group 0;");
        __syncthreads();
        if (i + 2 < 8) load_stage((i+2)%3, (i+2)*64);

        const int s = i % 3;
        const __nv_bfloat16* Ab = As + s*128*GA_STRIDE;
        const __nv_bfloat16* Bb = Bs + s*64*GB_STRIDE;
        #pragma unroll
        for (int kk = 0; kk < 64; kk += 16) {
            wmma::fragment<wmma::matrix_a,16,16,16,__nv_bfloat16,wmma::row_major> af[2];
            wmma::fragment<wmma::matrix_b,16,16,16,__nv_bfloat16,wmma::row_major> bf[4];
            #pragma unroll
            for (int ii = 0; ii < 2; ii++)
                wmma::load_matrix_sync(af[ii], Ab + (wm*32 + ii*16)*GA_STRIDE + kk, GA_STRIDE);
            #pragma unroll
            for (int j = 0; j < 4; j++)
                wmma::load_matrix_sync(bf[j], Bb + kk*GB_STRIDE + wn*64 + j*16, GB_STRIDE);
            #pragma unroll
            for (int ii = 0; ii < 2; ii++)
                #pragma unroll
                for (int j = 0; j < 4; j++)
                    wmma::mma_sync(acc[ii][j], af[ii], bf[j], acc[ii][j]);
        }
        __syncthreads();
    }
    #pragma unroll
    for (int ii = 0; ii < 2; ii++)
        #pragma unroll
        for (int j = 0; j < 4; j++)
            wmma::store_matrix_sync(
                Cg + (size_t)(bm*128 + wm*32 + ii*16)*NN + bn*128 + wn*64 + j*16,
                acc[ii][j], NN, wmma::mem_row_major);
}

// ---------------------------------------------------------------------------
// K3a (k_pep): peptide stencil only — INDEPENDENT of the GEMM, overlaps it.
// 2 CTAs/row (y-halves + halo), c[18] register column, LDG/STS staging
// (cpa4 reverted — it regressed R10). pepsum goes to g_psum (global).
// ---------------------------------------------------------------------------
__global__ __launch_bounds__(512) void k_pep(
    const float* __restrict__ state, const float* __restrict__ firing,
    const float* __restrict__ D, const float* __restrict__ prod,
    const float* __restrict__ decay, const float* __restrict__ act,
    float* __restrict__ out_state)
{
    __shared__ float pep_s[18*512];   // 18 y-rows x 32 x x 16 p = 36KB

    const int row  = blockIdx.x >> 1;
    const int half = blockIdx.x & 1;
    const int y0   = half * 16;
    const int t = threadIdx.x;
    const size_t base = (size_t)row * SSTRIDE;
    const float* pep_g = state + base + PEP_OFF;
    float* outp = out_state + base + PEP_OFF;

    // Stage 18 y-rows (halo-inclusive): plain LDG->STS, coalesced, deep MLP
    #pragma unroll
    for (int i = t; i < 18*512; i += 512) {
        const int gy = (y0 + (i >> 9) + 31) & 31;    // y0 - 1 + ys, wrapped
        pep_s[i] = pep_g[gy*512 + (i & 511)];
    }
    __syncthreads();

    const int p  = t & 15;      // peptide channel
    const int xw = t >> 4;      // x coordinate (0..31)
    const int xl = (xw + 31) & 31, xr = (xw + 1) & 31;
    const float dd = fabsf(D[p]);
    const float pr = fabsf(prod[p]);
    const float de = fabsf(decay[p]);

    // Preload this thread's y column (center + halos): independent LDS
    float c[18];
    #pragma unroll
    for (int ys = 0; ys < 18; ys++)
        c[ys] = pep_s[ys*512 + xw*16 + p];

    #pragma unroll
    for (int j = 0; j < 16; j++) {          // local y; smem ys = j+1
        const int ng = (y0 + j)*32 + xw;
        const float cc  = c[j+1];
        const float lap = c[j] + c[j+2]
                        + pep_s[(j+1)*512 + xl*16 + p]
                        + pep_s[(j+1)*512 + xr*16 + p]
                        - 4.0f * cc;
        const float fir = firing[row*NN + ng];
        outp[ng*NP + p] = cc + DT_F*(pr*fir - de*cc + dd*lap);
    }

    // pepsum -> global: lane l handles quad q=l&3 of neuron w*8+(l>>2)
    {
        const int lane = t & 31, w = t >> 5;
        const int q = lane & 3;
        const float4 aq = *(const float4*)(act + q*4);
        #pragma unroll
        for (int i = 0; i < 4; i++) {
            const int nl = i*128 + w*8 + (lane >> 2);      // local neuron
            const float4 v = *(const float4*)(pep_s + 512 + nl*NP + q*4);
            float part = v.x*aq.x + v.y*aq.y + v.z*aq.z + v.w*aq.w;
            part += __shfl_xor_sync(0xffffffffu, part, 1);
            part += __shfl_xor_sync(0xffffffffu, part, 2);
            if (q == 0) g_psum[(size_t)row*NN + half*512 + nl] = part;
        }
    }
}

// ---------------------------------------------------------------------------
// K3b (k_neuron): neuron integration — needs gemm partials + g_psum.
// Pure elementwise, fully coalesced.
// ---------------------------------------------------------------------------
__global__ __launch_bounds__(256) void k_neuron(
    const float* __restrict__ state, const float* __restrict__ u,
    const float* __restrict__ ndecay, const float* __restrict__ input_layer,
    float* __restrict__ out_state)
{
    const int idx = blockIdx.x * 256 + threadIdx.x;   // NBATCH*NN threads
    const int row = idx >> 10;
    const int n   = idx & (NN - 1);
    const size_t base = (size_t)row * SSTRIDE;
    const float ndec = fabsf(ndecay[0]);
    const float uval = u[row];
    const float pc2  = state[base + PC2_OFF];
    const float ab = state[base + n];
    const float ne = state[base + NEU_OFF + n] * ab;
    const float syn = g_dsyn[idx] + g_dsyn2[idx];
    const float dn = g_psum[idx]*pc2 + syn - ne*ndec + input_layer[n]*uval;
    out_state[base + NEU_OFF + n] = (ne + dn*DT_F) * ab;
}

// ---------------------------------------------------------------------------
// Graph-captured fork/join: side stream runs cvt + gemm, main (capture)
// stream runs firing + pep + neuron. gemm overlaps pep.
// Streams/events created once on the (uncaptured) correctness call; the
// captured work is identical on every call.
// ---------------------------------------------------------------------------
extern "C" void kernel_launch(void* const* d_in, const int* in_sizes, int n_in,
                              void* d_out, int out_size)
{
    const float* u       = (const float*)d_in[0];
    const float* state   = (const float*)d_in[1];
    const float* noise_u = (const float*)d_in[2];
    const float* D       = (const float*)d_in[3];
    const float* prod    = (const float*)d_in[4];
    const float* decay   = (const float*)d_in[5];
    const float* act     = (const float*)d_in[6];
    const float* syn     = (const float*)d_in[7];
    const float* ndec    = (const float*)d_in[8];
    const float* inl     = (const float*)d_in[9];

    float* out        = (float*)d_out;
    float* out_firing = out;
    float* out_state  = out + (size_t)NBATCH*NN;

    static cudaStream_t s2 = nullptr;
    static cudaEvent_t eFork = nullptr, eFir = nullptr, eGemm = nullptr;
    if (s2 == nullptr) {
        cudaStreamCreateWithFlags(&s2, cudaStreamNonBlocking);
        cudaEventCreateWithFlags(&eFork, cudaEventDisableTiming);
        cudaEventCreateWithFlags(&eFir,  cudaEventDisableTiming);
        cudaEventCreateWithFlags(&eGemm, cudaEventDisableTiming);
        cudaFuncSetAttribute(k_gemm, cudaFuncAttributeMaxDynamicSharedMemorySize,
                             GEMM_SMEM);
    }

    // fork side stream from the capture-origin stream
    cudaEventRecord(eFork, 0);
    cudaStreamWaitEvent(s2, eFork, 0);

    k_cvt<<<(NN*NN/4)/256, 256, 0, s2>>>(syn);          // ∥ with firing
    k_firing<<<(NBATCH*NN)/256, 256>>>(state, noise_u, out_firing, out_state);

    cudaEventRecord(eFir, 0);                           // gemm needs firing
    cudaStreamWaitEvent(s2, eFir, 0);
    dim3 gg(NN/128, NBATCH/128, 2);                     // 256 CTAs (split-K)
    k_gemm<<<gg, 256, GEMM_SMEM, s2>>>();
    cudaEventRecord(eGemm, s2);

    k_pep<<<NBATCH*2, 512>>>(state, out_firing, D, prod, decay, act, out_state);

    cudaStreamWaitEvent(0, eGemm, 0);                   // join before integrate
    k_neuron<<<(NBATCH*NN)/256, 256>>>(state, u, ndec, inl, out_state);
}